// round 5
// baseline (speedup 1.0000x reference)
#include <cuda_runtime.h>
#include <cstdint>

// ---------------------------------------------------------------------------
// MLGRUCell via exact bf16 tensor-core path:
//   quantized activations are exact integers in [-128,127]; sign weights are
//   {-1,0,+1}. Both exact in bf16, dot-128 exact in fp32 accum. HMMA m16n8k16
//   computes the ternary matmul bit-exactly.
// Gates: sigmoid(y) = 0.5*tanh(y/2)+0.5 via tanh.approx.f32 (3 MUFU/elem).
// A fragments are register-resident (64 regs) — no LDS re-read stream.
// ---------------------------------------------------------------------------

// B fragments bf16: [mat(3)][nt(16)][kt(8)][lane(32)] -> uint2 {b0,b1}
__device__ uint2 g_wfrag[3 * 16 * 8 * 32];

__device__ __forceinline__ unsigned sgn_bf16(float v) {
    return v > 0.f ? 0x3F80u : (v < 0.f ? 0xBF80u : 0u);
}

__global__ void prep_kernel(const float* __restrict__ Wf,
                            const float* __restrict__ Wc,
                            const float* __restrict__ Wg) {
    int idx = blockIdx.x * blockDim.x + threadIdx.x;
    if (idx >= 3 * 16 * 8 * 32) return;
    int lane = idx & 31;
    int kt   = (idx >> 5) & 7;
    int nt   = (idx >> 8) & 15;
    int mat  = idx >> 12;
    const float* W = (mat == 0) ? Wf : ((mat == 1) ? Wc : Wg);
    int g = lane >> 2, tig = lane & 3;
    // B[k][n] = sign(W[n][k]); W row-major [hidden=128][in=128]
    int n  = nt * 8 + g;
    int k0 = kt * 16 + tig * 2;
    uint2 r;
    r.x = sgn_bf16(W[n * 128 + k0])     | (sgn_bf16(W[n * 128 + k0 + 1]) << 16);
    r.y = sgn_bf16(W[n * 128 + k0 + 8]) | (sgn_bf16(W[n * 128 + k0 + 9]) << 16);
    g_wfrag[idx] = r;
}

#define MMA_OP(D, A, b0, b1)                                                   \
    asm volatile(                                                              \
        "mma.sync.aligned.m16n8k16.row.col.f32.bf16.bf16.f32 "                 \
        "{%0,%1,%2,%3}, {%4,%5,%6,%7}, {%8,%9}, {%0,%1,%2,%3};\n"              \
        : "+f"(D[0]), "+f"(D[1]), "+f"(D[2]), "+f"(D[3])                       \
        : "r"(A.x), "r"(A.y), "r"(A.z), "r"(A.w), "r"(b0), "r"(b1))

__device__ __forceinline__ float tanh_ap(float x) {
    float y;
    asm("tanh.approx.f32 %0, %1;" : "=f"(y) : "f"(x));
    return y;
}

__global__ __launch_bounds__(128, 4) void mlgru_kernel(
    const float* __restrict__ x, const float* __restrict__ hprev,
    const float* __restrict__ bf_, const float* __restrict__ bc_,
    const float* __restrict__ bg_, float* __restrict__ out, int half) {
    // A fragments: [mtile(8)][ktile(8)][lane(32)] -> uint4 (a0..a3)
    __shared__ uint4 qfrag[8][8][32];
    __shared__ float sinv[128];        // 0.5 * (maxabs/127) per row
    __shared__ float bias_sh[3][128];  // 0.5 * bias

    const int tid = threadIdx.x;
    const int w = tid >> 5, l = tid & 31;
    const int rowBlock = blockIdx.x * 128;

    bias_sh[0][tid] = 0.5f * bf_[tid];
    bias_sh[1][tid] = 0.5f * bc_[tid];
    bias_sh[2][tid] = 0.5f * bg_[tid];

    // ------------------- Phase 1: layernorm + quant -------------------
    // 4 rows per warp-iteration; lane l: row (l>>3), cols (l&7)*4 + 32j.
    {
        const int clb = (l & 7) * 4;
        #pragma unroll 1
        for (int it = 0; it < 8; it++) {
            const int r = w * 32 + it * 4 + (l >> 3);
            const float4* xr = (const float4*)(x + (rowBlock + r) * 128);
            float4 v[4];
            #pragma unroll
            for (int j = 0; j < 4; j++) v[j] = xr[(clb >> 2) + 8 * j];

            float s1 = 0.f, s2 = 0.f;
            #pragma unroll
            for (int j = 0; j < 4; j++) {
                s1 += v[j].x + v[j].y + v[j].z + v[j].w;
                s2 += v[j].x * v[j].x + v[j].y * v[j].y +
                      v[j].z * v[j].z + v[j].w * v[j].w;
            }
            #pragma unroll
            for (int m = 1; m <= 4; m <<= 1) {
                s1 += __shfl_xor_sync(0xffffffffu, s1, m);
                s2 += __shfl_xor_sync(0xffffffffu, s2, m);
            }
            const float mean = s1 * (1.f / 128.f);
            const float var  = s2 * (1.f / 128.f) - mean * mean;
            const float rstd = 1.f / sqrtf(var + 1e-8f);

            float xn[16];
            float mx = 0.f;
            #pragma unroll
            for (int j = 0; j < 4; j++) {
                xn[4*j+0] = (v[j].x - mean) * rstd;
                xn[4*j+1] = (v[j].y - mean) * rstd;
                xn[4*j+2] = (v[j].z - mean) * rstd;
                xn[4*j+3] = (v[j].w - mean) * rstd;
                mx = fmaxf(mx, fabsf(xn[4*j+0]));
                mx = fmaxf(mx, fabsf(xn[4*j+1]));
                mx = fmaxf(mx, fabsf(xn[4*j+2]));
                mx = fmaxf(mx, fabsf(xn[4*j+3]));
            }
            #pragma unroll
            for (int m = 1; m <= 4; m <<= 1)
                mx = fmaxf(mx, __shfl_xor_sync(0xffffffffu, mx, m));

            const float s = 127.f / mx;
            if ((l & 7) == 0) sinv[r] = 0.5f * mx * (1.f / 127.f);

            const int mt = r >> 4, g8 = r & 7, hi2 = (r >> 3) & 1;
            #pragma unroll
            for (int j = 0; j < 4; j++) {
                float q[4];
                #pragma unroll
                for (int e = 0; e < 4; e++)
                    q[e] = fminf(fmaxf(rintf(s * xn[4*j+e]), -128.f), 127.f);
                #pragma unroll
                for (int p = 0; p < 2; p++) {
                    const int c0 = clb + 32 * j + 2 * p;
                    // bf16 of small ints == high 16 bits of the fp32 (exact)
                    unsigned u = (__float_as_uint(q[2*p]) >> 16) |
                                 (__float_as_uint(q[2*p+1]) & 0xFFFF0000u);
                    const int kt  = c0 >> 4;
                    const int tg  = (c0 >> 1) & 3;
                    const int khi = (c0 >> 3) & 1;
                    ((unsigned*)&qfrag[mt][kt][(g8 << 2) | tg])[hi2 | (khi << 1)] = u;
                }
            }
        }
    }
    __syncthreads();

    // ------------------- Phase 2: 3 ternary MMAs + gates -------------------
    const int g = l >> 2, tig = l & 3;

    // A fragments register-resident: 2 m-tiles per warp, 8 k-tiles = 64 regs
    uint4 A[2][8];
    #pragma unroll
    for (int kt = 0; kt < 8; kt++) {
        A[0][kt] = qfrag[2 * w][kt][l];
        A[1][kt] = qfrag[2 * w + 1][kt][l];
    }

    // 0.5*dequant-scale per (mtile, row-half)
    float sih[2][2];
    #pragma unroll
    for (int mt = 0; mt < 2; mt++)
        #pragma unroll
        for (int rh = 0; rh < 2; rh++)
            sih[mt][rh] = sinv[w * 32 + mt * 16 + g + rh * 8];

    const uint2* wbase = g_wfrag + l;

    #pragma unroll 1
    for (int nt = 0; nt < 16; nt++) {    // 8 output columns per chunk
        float acc[3][2][4];
        #pragma unroll
        for (int m_ = 0; m_ < 3; m_++)
            #pragma unroll
            for (int a_ = 0; a_ < 2; a_++)
                #pragma unroll
                for (int e_ = 0; e_ < 4; e_++) acc[m_][a_][e_] = 0.f;

        #pragma unroll
        for (int kt = 0; kt < 8; kt++) {
            #pragma unroll
            for (int mat = 0; mat < 3; mat++) {
                const uint2 Bv = wbase[((mat * 16 + nt) * 8 + kt) * 32];
                MMA_OP(acc[mat][0], A[0][kt], Bv.x, Bv.y);
                MMA_OP(acc[mat][1], A[1][kt], Bv.x, Bv.y);
            }
        }

        // Epilogue: z = 0.5*(dequant + bias); gates via tanh
        const int cbase = nt * 8 + tig * 2;
        const float2 bF = *(const float2*)&bias_sh[0][cbase];
        const float2 bC = *(const float2*)&bias_sh[1][cbase];
        const float2 bG = *(const float2*)&bias_sh[2][cbase];
        const float bFv[2] = {bF.x, bF.y};
        const float bCv[2] = {bC.x, bC.y};
        const float bGv[2] = {bG.x, bG.y};

        #pragma unroll
        for (int mt = 0; mt < 2; mt++) {
            const int rloc = w * 32 + mt * 16 + g;
            #pragma unroll
            for (int rh = 0; rh < 2; rh++) {
                const int row = rowBlock + rloc + rh * 8;
                const float si = sih[mt][rh];
                const float2 hp = *(const float2*)(hprev + row * 128 + cbase);
                const float hpv[2] = {hp.x, hp.y};
                const int i0 = rh * 2;
                float ov[2], hv[2];
                #pragma unroll
                for (int p = 0; p < 2; p++) {
                    const float zf = fmaf(acc[0][mt][i0+p], si, bFv[p]);
                    const float zc = fmaf(acc[1][mt][i0+p], si, bCv[p]);
                    const float zg = fmaf(acc[2][mt][i0+p], si, bGv[p]);
                    const float f  = fmaf(0.5f, tanh_ap(zf), 0.5f);
                    const float gg = fmaf(0.5f, tanh_ap(zg), 0.5f);
                    const float sc = fmaf(0.5f, tanh_ap(zc), 0.5f);
                    const float cv = (zc + zc) * sc;      // silu(y)=y*sig(y)
                    const float h  = fmaf(f, hpv[p] - cv, cv);
                    hv[p] = h;
                    ov[p] = gg * h;
                }
                *(float2*)(out + row * 128 + cbase)        = make_float2(ov[0], ov[1]);
                *(float2*)(out + half + row * 128 + cbase) = make_float2(hv[0], hv[1]);
            }
        }
    }
}

extern "C" void kernel_launch(void* const* d_in, const int* in_sizes, int n_in,
                              void* d_out, int out_size) {
    const float* x  = (const float*)d_in[0];
    const float* h  = (const float*)d_in[1];
    const float* Wf = (const float*)d_in[2];
    const float* Wc = (const float*)d_in[3];
    const float* Wg = (const float*)d_in[4];
    const float* bf = (const float*)d_in[5];
    const float* bc = (const float*)d_in[6];
    const float* bg = (const float*)d_in[7];
    float* out = (float*)d_out;

    prep_kernel<<<96, 128>>>(Wf, Wc, Wg);

    const int rows = in_sizes[0] / 128;      // 262144
    const int blocks = rows / 128;           // 2048
    const int half = out_size / 2;
    mlgru_kernel<<<blocks, 128>>>(x, h, bf, bc, bg, out, half);
}

// round 6
// speedup vs baseline: 1.1682x; 1.1682x over previous
#include <cuda_runtime.h>
#include <cstdint>

// ---------------------------------------------------------------------------
// MLGRUCell via exact bf16 tensor-core path (HMMA m16n8k16):
//   quantized activations are exact ints in [-128,127]; sign weights {-1,0,+1}
//   -> both exact in bf16, K=128 dot exact in fp32 accum.
// Gates: sigmoid(y)=0.5*tanh(y/2)+0.5 via tanh.approx.f32.
// B is packed with a COLUMN PERMUTATION so each thread owns 4 contiguous
// output columns -> float4 epilogue; hprev is software-prefetched per chunk.
// ---------------------------------------------------------------------------

// B fragments bf16: [mat(3)][ch(8)][kt(8)][lane(32)] -> uint4
//  .x/.y = b0/b1 of even (permuted) tile, .z/.w = odd tile.
//  Tile n-index j maps to actual column: ch*16 + (j>>1)*4 + 2*s + (j&1).
__device__ uint4 g_wfrag[3 * 8 * 8 * 32];

__device__ __forceinline__ unsigned sgn_bf16(float v) {
    return v > 0.f ? 0x3F80u : (v < 0.f ? 0xBF80u : 0u);
}

__global__ void prep_kernel(const float* __restrict__ Wf,
                            const float* __restrict__ Wc,
                            const float* __restrict__ Wg) {
    int idx = blockIdx.x * blockDim.x + threadIdx.x;
    if (idx >= 3 * 8 * 8 * 32) return;
    int lane = idx & 31;
    int kt   = (idx >> 5) & 7;
    int ch   = (idx >> 8) & 7;
    int mat  = idx >> 11;
    const float* W = (mat == 0) ? Wf : ((mat == 1) ? Wc : Wg);
    int g = lane >> 2, tig = lane & 3;
    // actual columns for tile n-index j=g, sub-tile s:
    int ne = ch * 16 + (g >> 1) * 4 + (g & 1);      // s=0
    int no = ne + 2;                                 // s=1
    int k0 = kt * 16 + tig * 2;
    uint4 r;
    // B[k][n] = sign(W[n][k]); W row-major [hidden=128][in=128]
    r.x = sgn_bf16(W[ne * 128 + k0])     | (sgn_bf16(W[ne * 128 + k0 + 1]) << 16);
    r.y = sgn_bf16(W[ne * 128 + k0 + 8]) | (sgn_bf16(W[ne * 128 + k0 + 9]) << 16);
    r.z = sgn_bf16(W[no * 128 + k0])     | (sgn_bf16(W[no * 128 + k0 + 1]) << 16);
    r.w = sgn_bf16(W[no * 128 + k0 + 8]) | (sgn_bf16(W[no * 128 + k0 + 9]) << 16);
    g_wfrag[idx] = r;
}

#define MMA_OP(D, A, b0, b1)                                                   \
    asm volatile(                                                              \
        "mma.sync.aligned.m16n8k16.row.col.f32.bf16.bf16.f32 "                 \
        "{%0,%1,%2,%3}, {%4,%5,%6,%7}, {%8,%9}, {%0,%1,%2,%3};\n"              \
        : "+f"(D[0]), "+f"(D[1]), "+f"(D[2]), "+f"(D[3])                       \
        : "r"(A.x), "r"(A.y), "r"(A.z), "r"(A.w), "r"(b0), "r"(b1))

__device__ __forceinline__ float tanh_ap(float x) {
    float y;
    asm("tanh.approx.f32 %0, %1;" : "=f"(y) : "f"(x));
    return y;
}

__global__ __launch_bounds__(128, 4) void mlgru_kernel(
    const float* __restrict__ x, const float* __restrict__ hprev,
    const float* __restrict__ bf_, const float* __restrict__ bc_,
    const float* __restrict__ bg_, float* __restrict__ out, int half) {
    // A fragments: [mtile(8)][ktile(8)][lane(32)] -> uint4 (a0..a3)
    __shared__ uint4 qfrag[8][8][32];
    __shared__ float sinv[128];        // 0.5 * (maxabs/127) per row
    __shared__ float bias_sh[3][128];  // 0.5 * bias

    const int tid = threadIdx.x;
    const int w = tid >> 5, l = tid & 31;
    const int rowBlock = blockIdx.x * 128;

    bias_sh[0][tid] = 0.5f * bf_[tid];
    bias_sh[1][tid] = 0.5f * bc_[tid];
    bias_sh[2][tid] = 0.5f * bg_[tid];

    // ------------------- Phase 1: layernorm + quant -------------------
    // 4 rows per warp-iteration; lane l: row (l>>3), cols (l&7)*4 + 32j.
    {
        const int clb = (l & 7) * 4;
        #pragma unroll 1
        for (int it = 0; it < 8; it++) {
            const int r = w * 32 + it * 4 + (l >> 3);
            const float4* xr = (const float4*)(x + (rowBlock + r) * 128);
            float4 v[4];
            #pragma unroll
            for (int j = 0; j < 4; j++) v[j] = xr[(clb >> 2) + 8 * j];

            float s1 = 0.f, s2 = 0.f;
            #pragma unroll
            for (int j = 0; j < 4; j++) {
                s1 += v[j].x + v[j].y + v[j].z + v[j].w;
                s2 += v[j].x * v[j].x + v[j].y * v[j].y +
                      v[j].z * v[j].z + v[j].w * v[j].w;
            }
            #pragma unroll
            for (int m = 1; m <= 4; m <<= 1) {
                s1 += __shfl_xor_sync(0xffffffffu, s1, m);
                s2 += __shfl_xor_sync(0xffffffffu, s2, m);
            }
            const float mean = s1 * (1.f / 128.f);
            const float var  = s2 * (1.f / 128.f) - mean * mean;
            const float rstd = 1.f / sqrtf(var + 1e-8f);

            float xn[16];
            float mx = 0.f;
            #pragma unroll
            for (int j = 0; j < 4; j++) {
                xn[4*j+0] = (v[j].x - mean) * rstd;
                xn[4*j+1] = (v[j].y - mean) * rstd;
                xn[4*j+2] = (v[j].z - mean) * rstd;
                xn[4*j+3] = (v[j].w - mean) * rstd;
                mx = fmaxf(mx, fabsf(xn[4*j+0]));
                mx = fmaxf(mx, fabsf(xn[4*j+1]));
                mx = fmaxf(mx, fabsf(xn[4*j+2]));
                mx = fmaxf(mx, fabsf(xn[4*j+3]));
            }
            #pragma unroll
            for (int m = 1; m <= 4; m <<= 1)
                mx = fmaxf(mx, __shfl_xor_sync(0xffffffffu, mx, m));

            const float s = 127.f / mx;
            if ((l & 7) == 0) sinv[r] = 0.5f * mx * (1.f / 127.f);

            const int mt = r >> 4, g8 = r & 7, hi2 = (r >> 3) & 1;
            #pragma unroll
            for (int j = 0; j < 4; j++) {
                float q[4];
                #pragma unroll
                for (int e = 0; e < 4; e++)
                    q[e] = fminf(fmaxf(rintf(s * xn[4*j+e]), -128.f), 127.f);
                #pragma unroll
                for (int p = 0; p < 2; p++) {
                    const int c0 = clb + 32 * j + 2 * p;
                    // bf16 of small ints == high 16 bits of fp32 (exact)
                    unsigned u = (__float_as_uint(q[2*p]) >> 16) |
                                 (__float_as_uint(q[2*p+1]) & 0xFFFF0000u);
                    const int kt  = c0 >> 4;
                    const int tg  = (c0 >> 1) & 3;
                    const int khi = (c0 >> 3) & 1;
                    ((unsigned*)&qfrag[mt][kt][(g8 << 2) | tg])[hi2 | (khi << 1)] = u;
                }
            }
        }
    }
    __syncthreads();

    // ------------------- Phase 2: 3 ternary MMAs + gates -------------------
    const int g = l >> 2, tig = l & 3;

    // 0.5*dequant-scale per (mtile, row-half)
    float sih[2][2];
    #pragma unroll
    for (int mt = 0; mt < 2; mt++)
        #pragma unroll
        for (int rh = 0; rh < 2; rh++)
            sih[mt][rh] = sinv[w * 32 + mt * 16 + g + rh * 8];

    const uint4* wbase = g_wfrag + l;

    #pragma unroll 1
    for (int ch = 0; ch < 8; ch++) {    // 16 output columns per chunk
        const int cbase = ch * 16 + tig * 4;   // 4 contiguous cols per thread

        // ---- prefetch hprev (float4 per (mt,rh)) ----
        float4 hp[2][2];
        #pragma unroll
        for (int mt = 0; mt < 2; mt++)
            #pragma unroll
            for (int rh = 0; rh < 2; rh++) {
                const int row = rowBlock + w * 32 + mt * 16 + g + rh * 8;
                hp[mt][rh] = *(const float4*)(hprev + row * 128 + cbase);
            }

        // acc[mat][mt][tile][4]
        float acc[3][2][2][4];
        #pragma unroll
        for (int m_ = 0; m_ < 3; m_++)
            #pragma unroll
            for (int a_ = 0; a_ < 2; a_++)
                #pragma unroll
                for (int t_ = 0; t_ < 2; t_++)
                    #pragma unroll
                    for (int e_ = 0; e_ < 4; e_++) acc[m_][a_][t_][e_] = 0.f;

        #pragma unroll
        for (int kt = 0; kt < 8; kt++) {
            const uint4 A0 = qfrag[2 * w][kt][l];
            const uint4 A1 = qfrag[2 * w + 1][kt][l];
            #pragma unroll
            for (int mat = 0; mat < 3; mat++) {
                const uint4 Bv = wbase[((mat * 8 + ch) * 8 + kt) * 32];
                MMA_OP(acc[mat][0][0], A0, Bv.x, Bv.y);
                MMA_OP(acc[mat][1][0], A1, Bv.x, Bv.y);
                MMA_OP(acc[mat][0][1], A0, Bv.z, Bv.w);
                MMA_OP(acc[mat][1][1], A1, Bv.z, Bv.w);
            }
        }

        // ---- epilogue: 4 contiguous cols/thread, float4 stores ----
        const float4 bF = *(const float4*)&bias_sh[0][cbase];
        const float4 bC = *(const float4*)&bias_sh[1][cbase];
        const float4 bG = *(const float4*)&bias_sh[2][cbase];
        const float bFv[4] = {bF.x, bF.y, bF.z, bF.w};
        const float bCv[4] = {bC.x, bC.y, bC.z, bC.w};
        const float bGv[4] = {bG.x, bG.y, bG.z, bG.w};

        #pragma unroll
        for (int mt = 0; mt < 2; mt++) {
            #pragma unroll
            for (int rh = 0; rh < 2; rh++) {
                const int row = rowBlock + w * 32 + mt * 16 + g + rh * 8;
                const float si = sih[mt][rh];
                const float hpv[4] = {hp[mt][rh].x, hp[mt][rh].y,
                                      hp[mt][rh].z, hp[mt][rh].w};
                float ov[4], hv[4];
                #pragma unroll
                for (int c = 0; c < 4; c++) {
                    // col c: tile = c>>1, elem = rh*2 + (c&1)
                    const int t_ = c >> 1, e_ = rh * 2 + (c & 1);
                    const float zf = fmaf(acc[0][mt][t_][e_], si, bFv[c]);
                    const float zc = fmaf(acc[1][mt][t_][e_], si, bCv[c]);
                    const float zg = fmaf(acc[2][mt][t_][e_], si, bGv[c]);
                    const float f  = fmaf(0.5f, tanh_ap(zf), 0.5f);
                    const float gg = fmaf(0.5f, tanh_ap(zg), 0.5f);
                    const float sc = fmaf(0.5f, tanh_ap(zc), 0.5f);
                    const float cv = (zc + zc) * sc;      // silu
                    const float h  = fmaf(f, hpv[c] - cv, cv);
                    hv[c] = h;
                    ov[c] = gg * h;
                }
                *(float4*)(out + row * 128 + cbase) =
                    make_float4(ov[0], ov[1], ov[2], ov[3]);
                *(float4*)(out + half + row * 128 + cbase) =
                    make_float4(hv[0], hv[1], hv[2], hv[3]);
            }
        }
    }
}

extern "C" void kernel_launch(void* const* d_in, const int* in_sizes, int n_in,
                              void* d_out, int out_size) {
    const float* x  = (const float*)d_in[0];
    const float* h  = (const float*)d_in[1];
    const float* Wf = (const float*)d_in[2];
    const float* Wc = (const float*)d_in[3];
    const float* Wg = (const float*)d_in[4];
    const float* bf = (const float*)d_in[5];
    const float* bc = (const float*)d_in[6];
    const float* bg = (const float*)d_in[7];
    float* out = (float*)d_out;

    prep_kernel<<<48, 128>>>(Wf, Wc, Wg);

    const int rows = in_sizes[0] / 128;      // 262144
    const int blocks = rows / 128;           // 2048
    const int half = out_size / 2;
    mlgru_kernel<<<blocks, 128>>>(x, h, bf, bc, bg, out, half);
}